// round 15
// baseline (speedup 1.0000x reference)
#include <cuda_runtime.h>
#include <cuda_fp16.h>
#include <cstdint>
#include <math.h>

// ---------------------------------------------------------------------------
// Problem constants
// ---------------------------------------------------------------------------
#define B_  8
#define L_  2048
#define C_  512
#define CI_ 256
#define MT_ 16384   // B_*L_

typedef __half hf;

// ---------------------------------------------------------------------------
// Scratch (__device__ globals; allocation-free)
// ---------------------------------------------------------------------------
__device__ hf    g_inH [(size_t)MT_ * C_];           // inputs hi  [bl][c]
__device__ hf    g_inL [(size_t)MT_ * C_];           // inputs lo
__device__ hf    g_xyH [(size_t)MT_ * C_];           // [x_proj | y_proj] hi [bl][512]
__device__ hf    g_xyL [(size_t)MT_ * C_];
__device__ hf    g_otH [(size_t)C_ * MT_];           // o_proj^T single plane [c][bl]
__device__ hf    g_scH [(size_t)B_ * L_ * L_];       // logits hi  [b][l][m]
__device__ hf    g_scL [(size_t)B_ * L_ * L_];       // logits lo
__device__ hf    g_atH [(size_t)B_ * L_ * L_];       // attn single plane [b][l][m]
__device__ hf    g_wxyH[C_ * C_], g_wxyL[C_ * C_];   // [WxT ; WyT], [n][c]
__device__ hf    g_wotH[C_ * C_], g_wotL[C_ * C_];   // WoT [d][c]
__device__ float g_bxy[C_];                          // concat(bx, by)
__device__ float g_bo [C_];                          // bo copy

// ---------------------------------------------------------------------------
// helpers
// ---------------------------------------------------------------------------
__device__ __forceinline__ uint32_t smem_u32(const void* p) {
    uint32_t a;
    asm("{ .reg .u64 t; cvta.to.shared.u64 t, %1; cvt.u32.u64 %0, t; }"
        : "=r"(a) : "l"(p));
    return a;
}
__device__ __forceinline__ void splitf(float v, hf& h, hf& l) {
    h = __float2half_rn(v);
    l = __float2half_rn(v - __half2float(h));
}
__device__ __forceinline__ uint32_t pack2(hf a, hf b) {
    return (uint32_t)__half_as_ushort(a) |
           ((uint32_t)__half_as_ushort(b) << 16);
}

#define CP16(dst, src) \
    asm volatile("cp.async.ca.shared.global [%0], [%1], 16;" :: "r"(dst), "l"(src) : "memory")
#define CP_COMMIT() asm volatile("cp.async.commit_group;" ::: "memory")
#define CP_WAIT(n)  asm volatile("cp.async.wait_group %0;" :: "n"(n) : "memory")

#define LDSM_X4(r, a) \
    asm volatile("ldmatrix.sync.aligned.m8n8.x4.shared.b16 {%0,%1,%2,%3}, [%4];" \
        : "=r"((r)[0]), "=r"((r)[1]), "=r"((r)[2]), "=r"((r)[3]) : "r"(a))

__device__ __forceinline__ void mma_f16(float* d, const uint32_t* a, const uint32_t* b) {
    asm("mma.sync.aligned.m16n8k16.row.col.f32.f16.f16.f32 "
        "{%0,%1,%2,%3}, {%4,%5,%6,%7}, {%8,%9}, {%0,%1,%2,%3};"
        : "+f"(d[0]), "+f"(d[1]), "+f"(d[2]), "+f"(d[3])
        : "r"(a[0]), "r"(a[1]), "r"(a[2]), "r"(a[3]), "r"(b[0]), "r"(b[1]));
}

// ---------------------------------------------------------------------------
// GEMM core: 128x128 CTA tile, K-chunk 32, 64B swizzled rows, 3-stage ring,
// single sync/chunk, 8 warps (4M x 2N), warp tile 32x64.
// NTERM=3: A HL, B HL -> ah*bh + ah*bl + al*bh   (4 tiles/stage)
// NTERM=2: A HL, B H  -> ah*bh + al*bh           (3 tiles/stage)
// NTERM=1: A H,  B H  -> ah*bh                   (2 tiles/stage)
// ---------------------------------------------------------------------------
#define ROWB    64u
#define TILE_B  8192u
#define NSTAGE  3
#define NTHREADS 256
#define SMEM_T(n) (NSTAGE * ((n) + 1) * 8192)

template<int NTERM>
__device__ __forceinline__ void stage_copy(
    uint32_t stage,
    const hf* __restrict__ AH, const hf* __restrict__ AL, int ldA, int m0,
    const hf* __restrict__ BH, const hf* __restrict__ BL, int ldB, int n0,
    int k0, int tid)
{
    constexpr uint32_t B_OFF = (NTERM >= 2 ? 2u : 1u) * TILE_B;
    #pragma unroll
    for (int j = 0; j < 2; ++j) {
        const int seg = tid + NTHREADS * j;
        const int r = seg >> 2, c = seg & 3;
        const int csw = c ^ ((r >> 1) & 3);
        const uint32_t off = (uint32_t)r * ROWB + (uint32_t)csw * 16u;
        const size_t sa = (size_t)(m0 + r) * ldA + k0 + c * 8;
        const size_t sb = (size_t)(n0 + r) * ldB + k0 + c * 8;
        CP16(stage + off, AH + sa);
        if (NTERM >= 2) CP16(stage + TILE_B + off, AL + sa);
        CP16(stage + B_OFF + off, BH + sb);
        if (NTERM == 3) CP16(stage + B_OFF + TILE_B + off, BL + sb);
    }
}

template<int KTOT, int NTERM>
__device__ __forceinline__ void gemm_core(
    float acc[2][8][4],
    const hf* __restrict__ aH, const hf* __restrict__ aL, int ldA, int m0,
    const hf* __restrict__ bH, const hf* __restrict__ bL, int ldB, int n0,
    uint32_t smem_base, int tid, int wm, int wn, int lane)
{
    constexpr int NC = KTOT / 32;
    constexpr uint32_t STG   = (uint32_t)(NTERM + 1) * TILE_B;
    constexpr uint32_t B_OFF = (NTERM >= 2 ? 2u : 1u) * TILE_B;

    const uint32_t key  = (uint32_t)(((lane & 7) >> 1) & 3);
    const uint32_t aRow = (uint32_t)(wm + (lane & 7) + ((lane >> 3) & 1) * 8) * ROWB;
    const uint32_t bRow = (uint32_t)(wn + (lane & 7) + ((lane >> 4) & 1) * 8) * ROWB;
    const uint32_t aCh  = (uint32_t)(lane >> 4);
    const uint32_t bCh  = (uint32_t)((lane >> 3) & 1);

    stage_copy<NTERM>(smem_base, aH, aL, ldA, m0, bH, bL, ldB, n0, 0, tid);
    CP_COMMIT();
    stage_copy<NTERM>(smem_base + STG, aH, aL, ldA, m0, bH, bL, ldB, n0, 32, tid);
    CP_COMMIT();

    uint32_t stage = smem_base;
    for (int kc = 0; kc < NC; ++kc) {
        if (kc + 1 < NC) { CP_WAIT(1); } else { CP_WAIT(0); }
        __syncthreads();

        #pragma unroll
        for (int ks = 0; ks < 2; ++ks) {
            uint32_t ah[2][4], al[2][4];
            const uint32_t aSw = ((uint32_t)(ks * 2) + aCh) ^ key;
            const uint32_t bSw = ((uint32_t)(ks * 2) + bCh) ^ key;
            #pragma unroll
            for (int mi = 0; mi < 2; ++mi) {
                const uint32_t base = stage + aRow + mi * (16u * ROWB) + aSw * 16u;
                LDSM_X4(ah[mi], base);
                if (NTERM >= 2) LDSM_X4(al[mi], base + TILE_B);
            }
            #pragma unroll
            for (int h = 0; h < 2; ++h) {
                uint32_t bh2[8], bl2[8];
                #pragma unroll
                for (int q = 0; q < 2; ++q) {
                    const uint32_t base = stage + B_OFF + bRow
                                        + (uint32_t)(h * 32 + q * 16) * ROWB + bSw * 16u;
                    LDSM_X4(bh2 + q * 4, base);
                    if (NTERM == 3) LDSM_X4(bl2 + q * 4, base + TILE_B);
                }
                #pragma unroll
                for (int njl = 0; njl < 4; ++njl) {
                    const int nj = h * 4 + njl;
                    #pragma unroll
                    for (int mi = 0; mi < 2; ++mi)
                        mma_f16(acc[mi][nj], ah[mi], bh2 + njl * 2);
                }
                if (NTERM == 3) {
                    #pragma unroll
                    for (int njl = 0; njl < 4; ++njl) {
                        const int nj = h * 4 + njl;
                        #pragma unroll
                        for (int mi = 0; mi < 2; ++mi)
                            mma_f16(acc[mi][nj], ah[mi], bl2 + njl * 2);
                    }
                }
                if (NTERM >= 2) {
                    #pragma unroll
                    for (int njl = 0; njl < 4; ++njl) {
                        const int nj = h * 4 + njl;
                        #pragma unroll
                        for (int mi = 0; mi < 2; ++mi)
                            mma_f16(acc[mi][nj], al[mi], bh2 + njl * 2);
                    }
                }
            }
        }

        if (kc + 2 < NC) {
            uint32_t wstage = stage + 2 * STG;
            if (wstage >= smem_base + NSTAGE * STG) wstage -= NSTAGE * STG;
            stage_copy<NTERM>(wstage, aH, aL, ldA, m0, bH, bL, ldB, n0, (kc + 2) * 32, tid);
            CP_COMMIT();
        }
        stage += STG;
        if (stage >= smem_base + NSTAGE * STG) stage = smem_base;
    }
}

// ---------------------------------------------------------------------------
// Fused projection + o_proj^T
// z=0: xy = in @ Wxy^T + bxy[n] -> fp16 HL      (3-term)   grid (4=n, 128=m, .)
// z=1: ot = WoT @ in^T + bo[m]  -> fp16 single  (2-term)   grid (4=m, 128=n, .)
// ---------------------------------------------------------------------------
__global__ __launch_bounds__(NTHREADS, 2) void gemm_projot()
{
    extern __shared__ char smem[];
    const uint32_t smem_base = smem_u32(smem);

    const int tid  = threadIdx.x;
    const int wid  = tid >> 5;
    const int lane = tid & 31;
    const int g    = lane >> 2;
    const int t4   = lane & 3;
    const int wm   = (wid & 3) * 32;
    const int wn   = (wid >> 2) * 64;

    const int zz = blockIdx.z;
    const int m0 = (zz == 0) ? blockIdx.y * 128 : blockIdx.x * 128;
    const int n0 = (zz == 0) ? blockIdx.x * 128 : blockIdx.y * 128;

    float acc[2][8][4] = {};
    if (zz == 0) {
        gemm_core<512, 3>(acc, g_inH, g_inL, C_, m0, g_wxyH, g_wxyL, C_, n0,
                          smem_base, tid, wm, wn, lane);
    } else {
        gemm_core<512, 2>(acc, g_wotH, g_wotL, C_, m0, g_inH, nullptr, C_, n0,
                          smem_base, tid, wm, wn, lane);
    }

    #pragma unroll
    for (int mi = 0; mi < 2; ++mi) {
        const int r0 = m0 + wm + mi * 16 + g;
        const int r1 = r0 + 8;
        const float bm0 = (zz == 1) ? g_bo[r0] : 0.f;
        const float bm1 = (zz == 1) ? g_bo[r1] : 0.f;
        #pragma unroll
        for (int nj = 0; nj < 8; ++nj) {
            const int col = n0 + wn + nj * 8 + 2 * t4;
            float2 v0 = make_float2(acc[mi][nj][0], acc[mi][nj][1]);
            float2 v1 = make_float2(acc[mi][nj][2], acc[mi][nj][3]);
            if (zz == 0) {
                const float2 bb = *(const float2*)&g_bxy[col];
                v0.x += bb.x; v0.y += bb.y; v1.x += bb.x; v1.y += bb.y;
                hf h0, l0, h1, l1;
                splitf(v0.x, h0, l0); splitf(v0.y, h1, l1);
                *(uint32_t*)&g_xyH[(size_t)r0 * C_ + col] = pack2(h0, h1);
                *(uint32_t*)&g_xyL[(size_t)r0 * C_ + col] = pack2(l0, l1);
                splitf(v1.x, h0, l0); splitf(v1.y, h1, l1);
                *(uint32_t*)&g_xyH[(size_t)r1 * C_ + col] = pack2(h0, h1);
                *(uint32_t*)&g_xyL[(size_t)r1 * C_ + col] = pack2(l0, l1);
            } else {
                v0.x += bm0; v0.y += bm0; v1.x += bm1; v1.y += bm1;
                *(uint32_t*)&g_otH[(size_t)r0 * MT_ + col] =
                    pack2(__float2half_rn(v0.x), __float2half_rn(v0.y));
                *(uint32_t*)&g_otH[(size_t)r1 * MT_ + col] =
                    pack2(__float2half_rn(v1.x), __float2half_rn(v1.y));
            }
        }
    }
}

// ---------------------------------------------------------------------------
// scores GEMM (fp16 3-term) -> logits as fp16 hi/lo planes (22-bit effective)
// ---------------------------------------------------------------------------
__global__ __launch_bounds__(NTHREADS, 2) void gemm_scores()
{
    extern __shared__ char smem[];
    const uint32_t smem_base = smem_u32(smem);

    const int tid  = threadIdx.x;
    const int wid  = tid >> 5;
    const int lane = tid & 31;
    const int g    = lane >> 2;
    const int t4   = lane & 3;
    const int wm   = (wid & 3) * 32;
    const int wn   = (wid >> 2) * 64;

    const int bz = blockIdx.z;
    const int m0 = blockIdx.y * 128;
    const int n0 = blockIdx.x * 128;
    const hf* aH = g_xyH + (size_t)bz * L_ * C_;
    const hf* aL = g_xyL + (size_t)bz * L_ * C_;
    const hf* bH = aH + CI_;
    const hf* bL = aL + CI_;

    float acc[2][8][4] = {};
    gemm_core<256, 3>(acc, aH, aL, C_, m0, bH, bL, C_, n0, smem_base, tid, wm, wn, lane);

    hf* SH = g_scH + (size_t)bz * L_ * L_;
    hf* SL = g_scL + (size_t)bz * L_ * L_;
    #pragma unroll
    for (int mi = 0; mi < 2; ++mi) {
        const int r0 = m0 + wm + mi * 16 + g;
        const int r1 = r0 + 8;
        #pragma unroll
        for (int nj = 0; nj < 8; ++nj) {
            const int col = n0 + wn + nj * 8 + 2 * t4;
            hf h0, l0, h1, l1;
            splitf(acc[mi][nj][0], h0, l0); splitf(acc[mi][nj][1], h1, l1);
            *(uint32_t*)&SH[(size_t)r0 * L_ + col] = pack2(h0, h1);
            *(uint32_t*)&SL[(size_t)r0 * L_ + col] = pack2(l0, l1);
            splitf(acc[mi][nj][2], h0, l0); splitf(acc[mi][nj][3], h1, l1);
            *(uint32_t*)&SH[(size_t)r1 * L_ + col] = pack2(h0, h1);
            *(uint32_t*)&SL[(size_t)r1 * L_ + col] = pack2(l0, l1);
        }
    }
}

// ---------------------------------------------------------------------------
// nn_out GEMM (fp16 1-term): out = inputs + attn @ o_proj
// ---------------------------------------------------------------------------
__global__ __launch_bounds__(NTHREADS, 2) void gemm_nnout(
    const float* __restrict__ inputs_, float* __restrict__ out_)
{
    extern __shared__ char smem[];
    const uint32_t smem_base = smem_u32(smem);

    const int tid  = threadIdx.x;
    const int wid  = tid >> 5;
    const int lane = tid & 31;
    const int g    = lane >> 2;
    const int t4   = lane & 3;
    const int wm   = (wid & 3) * 32;
    const int wn   = (wid >> 2) * 64;

    const int bz = blockIdx.z;
    const int m0 = blockIdx.y * 128;   // l
    const int n0 = blockIdx.x * 128;   // c
    const hf* aH = g_atH + (size_t)bz * L_ * L_;
    const hf* bH = g_otH + (size_t)bz * L_;        // row stride MT_

    float acc[2][8][4] = {};
    gemm_core<2048, 1>(acc, aH, nullptr, L_, m0, bH, nullptr, MT_, n0,
                       smem_base, tid, wm, wn, lane);

    const float* R = inputs_ + (size_t)bz * L_ * C_;
    float* O = out_ + (size_t)bz * L_ * C_;

    #pragma unroll
    for (int mi = 0; mi < 2; ++mi) {
        const int r0 = m0 + wm + mi * 16 + g;
        const int r1 = r0 + 8;
        #pragma unroll
        for (int nj = 0; nj < 8; ++nj) {
            const int col = n0 + wn + nj * 8 + 2 * t4;
            float2 v0 = make_float2(acc[mi][nj][0], acc[mi][nj][1]);
            float2 v1 = make_float2(acc[mi][nj][2], acc[mi][nj][3]);
            const float2 q0 = *(const float2*)&R[(size_t)r0 * C_ + col];
            const float2 q1 = *(const float2*)&R[(size_t)r1 * C_ + col];
            v0.x += q0.x; v0.y += q0.y; v1.x += q1.x; v1.y += q1.y;
            *(float2*)&O[(size_t)r0 * C_ + col] = v0;
            *(float2*)&O[(size_t)r1 * C_ + col] = v1;
        }
    }
}

// ---------------------------------------------------------------------------
// Decompose inputs f32 -> fp16 hi/lo; first blocks also copy biases
// ---------------------------------------------------------------------------
__global__ __launch_bounds__(256) void decomp_inputs(
    const float* __restrict__ src, int n4,
    const float* __restrict__ bx, const float* __restrict__ by,
    const float* __restrict__ bo)
{
    const int i = blockIdx.x * 256 + threadIdx.x;
    if (i < C_) {
        g_bxy[i] = (i < CI_) ? bx[i] : by[i - CI_];
        g_bo[i]  = bo[i];
    }
    if (i >= n4) return;
    const float4 v = ((const float4*)src)[i];
    hf h0, h1, h2, h3, l0, l1, l2, l3;
    splitf(v.x, h0, l0); splitf(v.y, h1, l1);
    splitf(v.z, h2, l2); splitf(v.w, h3, l3);
    ((uint2*)g_inH)[i] = make_uint2(pack2(h0, h1), pack2(h2, h3));
    ((uint2*)g_inL)[i] = make_uint2(pack2(l0, l1), pack2(l2, l3));
}

// ---------------------------------------------------------------------------
// Single prep kernel: z selects Wx / Wy / Wo transpose+decompose (fp16)
// ---------------------------------------------------------------------------
__global__ void prep_weights(const float* __restrict__ Wx,
                             const float* __restrict__ Wy,
                             const float* __restrict__ Wo)
{
    __shared__ float tbuf[32][33];
    const int zz = blockIdx.z;
    const int Cc = (zz == 2) ? C_ : CI_;
    if (blockIdx.x * 32 >= Cc) return;
    const float* src = (zz == 0) ? Wx : (zz == 1) ? Wy : Wo;
    hf* H = (zz == 0) ? g_wxyH : (zz == 1) ? g_wxyH + (size_t)CI_ * C_ : g_wotH;
    hf* L = (zz == 0) ? g_wxyL : (zz == 1) ? g_wxyL + (size_t)CI_ * C_ : g_wotL;

    const int bx = blockIdx.x * 32;
    const int by = blockIdx.y * 32;
    const int x = threadIdx.x, y = threadIdx.y;
    #pragma unroll
    for (int d = 0; d < 32; d += 8)
        tbuf[y + d][x] = src[(size_t)(by + y + d) * Cc + bx + x];
    __syncthreads();
    #pragma unroll
    for (int d = 0; d < 32; d += 8) {
        hf h, l;
        splitf(tbuf[x][y + d], h, l);
        H[(size_t)(bx + y + d) * C_ + by + x] = h;
        L[(size_t)(bx + y + d) * C_ + by + x] = l;
    }
}

// ---------------------------------------------------------------------------
// Softmax over batch axis: fp16 hi/lo logits -> fp16 attn (8 elems/thread)
// ---------------------------------------------------------------------------
__global__ __launch_bounds__(256) void softmax_batch()
{
    const size_t idx = ((size_t)blockIdx.x * 256 + threadIdx.x) * 8;
    const size_t stride = (size_t)L_ * L_;
    float v[B_][8];
    float mx[8];
    #pragma unroll
    for (int e = 0; e < 8; ++e) mx[e] = -INFINITY;
    #pragma unroll
    for (int b = 0; b < B_; ++b) {
        const uint4 ph = *(const uint4*)&g_scH[b * stride + idx];
        const uint4 pl = *(const uint4*)&g_scL[b * stride + idx];
        const uint32_t hw[4] = { ph.x, ph.y, ph.z, ph.w };
        const uint32_t lw[4] = { pl.x, pl.y, pl.z, pl.w };
        #pragma unroll
        for (int q = 0; q < 4; ++q) {
            const float2 h2 = __half22float2(*(const __half2*)&hw[q]);
            const float2 l2 = __half22float2(*(const __half2*)&lw[q]);
            v[b][q * 2 + 0] = h2.x + l2.x;
            v[b][q * 2 + 1] = h2.y + l2.y;
            mx[q * 2 + 0] = fmaxf(mx[q * 2 + 0], v[b][q * 2 + 0]);
            mx[q * 2 + 1] = fmaxf(mx[q * 2 + 1], v[b][q * 2 + 1]);
        }
    }
    float s[8] = {};
    #pragma unroll
    for (int b = 0; b < B_; ++b)
        #pragma unroll
        for (int e = 0; e < 8; ++e) {
            v[b][e] = __expf(v[b][e] - mx[e]);
            s[e] += v[b][e];
        }
    float inv[8];
    #pragma unroll
    for (int e = 0; e < 8; ++e) inv[e] = 1.f / s[e];
    #pragma unroll
    for (int b = 0; b < B_; ++b) {
        uint4 o;
        o.x = pack2(__float2half_rn(v[b][0] * inv[0]), __float2half_rn(v[b][1] * inv[1]));
        o.y = pack2(__float2half_rn(v[b][2] * inv[2]), __float2half_rn(v[b][3] * inv[3]));
        o.z = pack2(__float2half_rn(v[b][4] * inv[4]), __float2half_rn(v[b][5] * inv[5]));
        o.w = pack2(__float2half_rn(v[b][6] * inv[6]), __float2half_rn(v[b][7] * inv[7]));
        *(uint4*)&g_atH[b * stride + idx] = o;
    }
}

// ---------------------------------------------------------------------------
// Launch: inputs, Wx, bx, Wy, by, Wo, bo
// ---------------------------------------------------------------------------
extern "C" void kernel_launch(void* const* d_in, const int* in_sizes, int n_in,
                              void* d_out, int out_size)
{
    const float* inputs = (const float*)d_in[0];
    const float* Wx = (const float*)d_in[1];
    const float* bx = (const float*)d_in[2];
    const float* Wy = (const float*)d_in[3];
    const float* by = (const float*)d_in[4];
    const float* Wo = (const float*)d_in[5];
    const float* bo = (const float*)d_in[6];
    float* out = (float*)d_out;

    cudaFuncSetAttribute((const void*)gemm_projot,
                         cudaFuncAttributeMaxDynamicSharedMemorySize, SMEM_T(3));
    cudaFuncSetAttribute((const void*)gemm_scores,
                         cudaFuncAttributeMaxDynamicSharedMemorySize, SMEM_T(3));
    cudaFuncSetAttribute((const void*)gemm_nnout,
                         cudaFuncAttributeMaxDynamicSharedMemorySize, SMEM_T(1));

    // 0) decompose inputs (+bias copies), prep weights
    decomp_inputs<<<(MT_ * C_ / 4 + 255) / 256, 256>>>(inputs, MT_ * C_ / 4, bx, by, bo);
    prep_weights<<<dim3(16, 16, 3), dim3(32, 8)>>>(Wx, Wy, Wo);

    // 1) fused projection (3-term) + o_proj^T (2-term)
    gemm_projot<<<dim3(4, 128, 2), NTHREADS, SMEM_T(3)>>>();

    // 2) scores[b] = x_proj[b] @ y_proj[b]^T (3-term) -> fp16 hi/lo logits
    gemm_scores<<<dim3(L_ / 128, L_ / 128, B_), NTHREADS, SMEM_T(3)>>>();

    // 3) softmax over batch -> attn fp16 (single plane)
    softmax_batch<<<(L_ * L_ / 8) / 256, 256>>>();

    // 4) out[b] = inputs[b] + attn[b] @ o_proj[b]  (fp16 1-term)
    gemm_nnout<<<dim3(C_ / 128, L_ / 128, B_), NTHREADS, SMEM_T(1)>>>(inputs, out);
}

// round 16
// speedup vs baseline: 1.0270x; 1.0270x over previous
#include <cuda_runtime.h>
#include <cuda_fp16.h>
#include <cstdint>
#include <math.h>

// ---------------------------------------------------------------------------
// Problem constants
// ---------------------------------------------------------------------------
#define B_  8
#define L_  2048
#define C_  512
#define CI_ 256
#define MT_ 16384   // B_*L_

typedef __half hf;

// ---------------------------------------------------------------------------
// Scratch (__device__ globals; allocation-free)
// ---------------------------------------------------------------------------
__device__ hf    g_inH [(size_t)MT_ * C_];           // inputs hi  [bl][c]
__device__ hf    g_inL [(size_t)MT_ * C_];           // inputs lo
__device__ hf    g_xyH [(size_t)MT_ * C_];           // [x_proj | y_proj] hi [bl][512]
__device__ hf    g_xyL [(size_t)MT_ * C_];
__device__ hf    g_otH [(size_t)C_ * MT_];           // o_proj^T single plane [c][bl]
__device__ float g_scores[(size_t)B_ * L_ * L_];     // f32 logits
__device__ hf    g_atH [(size_t)B_ * L_ * L_];       // attn single plane [b][l][m]
__device__ hf    g_wxyH[C_ * C_], g_wxyL[C_ * C_];   // [WxT ; WyT], [n][c]
__device__ hf    g_wotH[C_ * C_], g_wotL[C_ * C_];   // WoT [d][c]
__device__ float g_bxy[C_];                          // concat(bx, by)
__device__ float g_bo [C_];                          // bo copy

// ---------------------------------------------------------------------------
// helpers
// ---------------------------------------------------------------------------
__device__ __forceinline__ uint32_t smem_u32(const void* p) {
    uint32_t a;
    asm("{ .reg .u64 t; cvta.to.shared.u64 t, %1; cvt.u32.u64 %0, t; }"
        : "=r"(a) : "l"(p));
    return a;
}
__device__ __forceinline__ void splitf(float v, hf& h, hf& l) {
    h = __float2half_rn(v);
    l = __float2half_rn(v - __half2float(h));
}
__device__ __forceinline__ uint32_t pack2(hf a, hf b) {
    return (uint32_t)__half_as_ushort(a) |
           ((uint32_t)__half_as_ushort(b) << 16);
}

#define CP16(dst, src) \
    asm volatile("cp.async.ca.shared.global [%0], [%1], 16;" :: "r"(dst), "l"(src) : "memory")
#define CP_COMMIT() asm volatile("cp.async.commit_group;" ::: "memory")
#define CP_WAIT(n)  asm volatile("cp.async.wait_group %0;" :: "n"(n) : "memory")

#define LDSM_X4(r, a) \
    asm volatile("ldmatrix.sync.aligned.m8n8.x4.shared.b16 {%0,%1,%2,%3}, [%4];" \
        : "=r"((r)[0]), "=r"((r)[1]), "=r"((r)[2]), "=r"((r)[3]) : "r"(a))

__device__ __forceinline__ void mma_f16(float* d, const uint32_t* a, const uint32_t* b) {
    asm("mma.sync.aligned.m16n8k16.row.col.f32.f16.f16.f32 "
        "{%0,%1,%2,%3}, {%4,%5,%6,%7}, {%8,%9}, {%0,%1,%2,%3};"
        : "+f"(d[0]), "+f"(d[1]), "+f"(d[2]), "+f"(d[3])
        : "r"(a[0]), "r"(a[1]), "r"(a[2]), "r"(a[3]), "r"(b[0]), "r"(b[1]));
}

// ---------------------------------------------------------------------------
// GEMM core: 128x128 CTA tile, K-chunk 32, 64B swizzled rows, NSTG-stage ring,
// single sync/chunk, 8 warps (4M x 2N), warp tile 32x64.
// NTERM=3: A HL, B HL -> ah*bh + ah*bl + al*bh   (4 tiles/stage)
// NTERM=2: A HL, B H  -> ah*bh + al*bh           (3 tiles/stage)
// NTERM=1: A H,  B H  -> ah*bh                   (2 tiles/stage)
// ---------------------------------------------------------------------------
#define ROWB    64u
#define TILE_B  8192u
#define NTHREADS 256
#define SMEM_TS(n, s) ((s) * ((n) + 1) * 8192)

template<int NTERM>
__device__ __forceinline__ void stage_copy(
    uint32_t stage,
    const hf* __restrict__ AH, const hf* __restrict__ AL, int ldA, int m0,
    const hf* __restrict__ BH, const hf* __restrict__ BL, int ldB, int n0,
    int k0, int tid)
{
    constexpr uint32_t B_OFF = (NTERM >= 2 ? 2u : 1u) * TILE_B;
    #pragma unroll
    for (int j = 0; j < 2; ++j) {
        const int seg = tid + NTHREADS * j;
        const int r = seg >> 2, c = seg & 3;
        const int csw = c ^ ((r >> 1) & 3);
        const uint32_t off = (uint32_t)r * ROWB + (uint32_t)csw * 16u;
        const size_t sa = (size_t)(m0 + r) * ldA + k0 + c * 8;
        const size_t sb = (size_t)(n0 + r) * ldB + k0 + c * 8;
        CP16(stage + off, AH + sa);
        if (NTERM >= 2) CP16(stage + TILE_B + off, AL + sa);
        CP16(stage + B_OFF + off, BH + sb);
        if (NTERM == 3) CP16(stage + B_OFF + TILE_B + off, BL + sb);
    }
}

template<int KTOT, int NTERM, int NSTG>
__device__ __forceinline__ void gemm_core(
    float acc[2][8][4],
    const hf* __restrict__ aH, const hf* __restrict__ aL, int ldA, int m0,
    const hf* __restrict__ bH, const hf* __restrict__ bL, int ldB, int n0,
    uint32_t smem_base, int tid, int wm, int wn, int lane)
{
    constexpr int NC = KTOT / 32;
    constexpr uint32_t STG   = (uint32_t)(NTERM + 1) * TILE_B;
    constexpr uint32_t B_OFF = (NTERM >= 2 ? 2u : 1u) * TILE_B;

    const uint32_t key  = (uint32_t)(((lane & 7) >> 1) & 3);
    const uint32_t aRow = (uint32_t)(wm + (lane & 7) + ((lane >> 3) & 1) * 8) * ROWB;
    const uint32_t bRow = (uint32_t)(wn + (lane & 7) + ((lane >> 4) & 1) * 8) * ROWB;
    const uint32_t aCh  = (uint32_t)(lane >> 4);
    const uint32_t bCh  = (uint32_t)((lane >> 3) & 1);

    #pragma unroll
    for (int i = 0; i < NSTG - 1; ++i) {
        stage_copy<NTERM>(smem_base + (uint32_t)i * STG,
                          aH, aL, ldA, m0, bH, bL, ldB, n0, i * 32, tid);
        CP_COMMIT();
    }

    uint32_t stage = smem_base;
    for (int kc = 0; kc < NC; ++kc) {
        CP_WAIT(NSTG - 2);
        __syncthreads();

        #pragma unroll
        for (int ks = 0; ks < 2; ++ks) {
            uint32_t ah[2][4], al[2][4];
            const uint32_t aSw = ((uint32_t)(ks * 2) + aCh) ^ key;
            const uint32_t bSw = ((uint32_t)(ks * 2) + bCh) ^ key;
            #pragma unroll
            for (int mi = 0; mi < 2; ++mi) {
                const uint32_t base = stage + aRow + mi * (16u * ROWB) + aSw * 16u;
                LDSM_X4(ah[mi], base);
                if (NTERM >= 2) LDSM_X4(al[mi], base + TILE_B);
            }
            #pragma unroll
            for (int h = 0; h < 2; ++h) {
                uint32_t bh2[8], bl2[8];
                #pragma unroll
                for (int q = 0; q < 2; ++q) {
                    const uint32_t base = stage + B_OFF + bRow
                                        + (uint32_t)(h * 32 + q * 16) * ROWB + bSw * 16u;
                    LDSM_X4(bh2 + q * 4, base);
                    if (NTERM == 3) LDSM_X4(bl2 + q * 4, base + TILE_B);
                }
                #pragma unroll
                for (int njl = 0; njl < 4; ++njl) {
                    const int nj = h * 4 + njl;
                    #pragma unroll
                    for (int mi = 0; mi < 2; ++mi)
                        mma_f16(acc[mi][nj], ah[mi], bh2 + njl * 2);
                }
                if (NTERM == 3) {
                    #pragma unroll
                    for (int njl = 0; njl < 4; ++njl) {
                        const int nj = h * 4 + njl;
                        #pragma unroll
                        for (int mi = 0; mi < 2; ++mi)
                            mma_f16(acc[mi][nj], ah[mi], bl2 + njl * 2);
                    }
                }
                if (NTERM >= 2) {
                    #pragma unroll
                    for (int njl = 0; njl < 4; ++njl) {
                        const int nj = h * 4 + njl;
                        #pragma unroll
                        for (int mi = 0; mi < 2; ++mi)
                            mma_f16(acc[mi][nj], al[mi], bh2 + njl * 2);
                    }
                }
            }
        }

        // prefetch chunk kc+NSTG-1 into the stage freed at kc-1; empty commit
        // otherwise to keep group counts uniform for CP_WAIT.
        if (kc + NSTG - 1 < NC) {
            uint32_t wstage = stage + (uint32_t)(NSTG - 1) * STG;
            if (wstage >= smem_base + (uint32_t)NSTG * STG)
                wstage -= (uint32_t)NSTG * STG;
            stage_copy<NTERM>(wstage, aH, aL, ldA, m0, bH, bL, ldB, n0,
                              (kc + NSTG - 1) * 32, tid);
        }
        CP_COMMIT();
        stage += STG;
        if (stage >= smem_base + (uint32_t)NSTG * STG) stage = smem_base;
    }
}

// ---------------------------------------------------------------------------
// Fused projection + o_proj^T
// z=0: xy = in @ Wxy^T + bxy[n] -> fp16 HL      (3-term)   grid (4=n, 128=m, .)
// z=1: ot = WoT @ in^T + bo[m]  -> fp16 single  (2-term)   grid (4=m, 128=n, .)
// ---------------------------------------------------------------------------
__global__ __launch_bounds__(NTHREADS, 2) void gemm_projot()
{
    extern __shared__ char smem[];
    const uint32_t smem_base = smem_u32(smem);

    const int tid  = threadIdx.x;
    const int wid  = tid >> 5;
    const int lane = tid & 31;
    const int g    = lane >> 2;
    const int t4   = lane & 3;
    const int wm   = (wid & 3) * 32;
    const int wn   = (wid >> 2) * 64;

    const int zz = blockIdx.z;
    const int m0 = (zz == 0) ? blockIdx.y * 128 : blockIdx.x * 128;
    const int n0 = (zz == 0) ? blockIdx.x * 128 : blockIdx.y * 128;

    float acc[2][8][4] = {};
    if (zz == 0) {
        gemm_core<512, 3, 3>(acc, g_inH, g_inL, C_, m0, g_wxyH, g_wxyL, C_, n0,
                             smem_base, tid, wm, wn, lane);
    } else {
        gemm_core<512, 2, 3>(acc, g_wotH, g_wotL, C_, m0, g_inH, nullptr, C_, n0,
                             smem_base, tid, wm, wn, lane);
    }

    #pragma unroll
    for (int mi = 0; mi < 2; ++mi) {
        const int r0 = m0 + wm + mi * 16 + g;
        const int r1 = r0 + 8;
        const float bm0 = (zz == 1) ? g_bo[r0] : 0.f;
        const float bm1 = (zz == 1) ? g_bo[r1] : 0.f;
        #pragma unroll
        for (int nj = 0; nj < 8; ++nj) {
            const int col = n0 + wn + nj * 8 + 2 * t4;
            float2 v0 = make_float2(acc[mi][nj][0], acc[mi][nj][1]);
            float2 v1 = make_float2(acc[mi][nj][2], acc[mi][nj][3]);
            if (zz == 0) {
                const float2 bb = *(const float2*)&g_bxy[col];
                v0.x += bb.x; v0.y += bb.y; v1.x += bb.x; v1.y += bb.y;
                hf h0, l0, h1, l1;
                splitf(v0.x, h0, l0); splitf(v0.y, h1, l1);
                *(uint32_t*)&g_xyH[(size_t)r0 * C_ + col] = pack2(h0, h1);
                *(uint32_t*)&g_xyL[(size_t)r0 * C_ + col] = pack2(l0, l1);
                splitf(v1.x, h0, l0); splitf(v1.y, h1, l1);
                *(uint32_t*)&g_xyH[(size_t)r1 * C_ + col] = pack2(h0, h1);
                *(uint32_t*)&g_xyL[(size_t)r1 * C_ + col] = pack2(l0, l1);
            } else {
                v0.x += bm0; v0.y += bm0; v1.x += bm1; v1.y += bm1;
                *(uint32_t*)&g_otH[(size_t)r0 * MT_ + col] =
                    pack2(__float2half_rn(v0.x), __float2half_rn(v0.y));
                *(uint32_t*)&g_otH[(size_t)r1 * MT_ + col] =
                    pack2(__float2half_rn(v1.x), __float2half_rn(v1.y));
            }
        }
    }
}

// ---------------------------------------------------------------------------
// scores GEMM (fp16 3-term, f32 out)
// ---------------------------------------------------------------------------
__global__ __launch_bounds__(NTHREADS, 2) void gemm_scores()
{
    extern __shared__ char smem[];
    const uint32_t smem_base = smem_u32(smem);

    const int tid  = threadIdx.x;
    const int wid  = tid >> 5;
    const int lane = tid & 31;
    const int g    = lane >> 2;
    const int t4   = lane & 3;
    const int wm   = (wid & 3) * 32;
    const int wn   = (wid >> 2) * 64;

    const int bz = blockIdx.z;
    const int m0 = blockIdx.y * 128;
    const int n0 = blockIdx.x * 128;
    const hf* aH = g_xyH + (size_t)bz * L_ * C_;
    const hf* aL = g_xyL + (size_t)bz * L_ * C_;
    const hf* bH = aH + CI_;
    const hf* bL = aL + CI_;

    float acc[2][8][4] = {};
    gemm_core<256, 3, 3>(acc, aH, aL, C_, m0, bH, bL, C_, n0,
                         smem_base, tid, wm, wn, lane);

    float* Cfb = g_scores + (size_t)bz * L_ * L_;
    #pragma unroll
    for (int mi = 0; mi < 2; ++mi) {
        const int r0 = m0 + wm + mi * 16 + g;
        const int r1 = r0 + 8;
        #pragma unroll
        for (int nj = 0; nj < 8; ++nj) {
            const int col = n0 + wn + nj * 8 + 2 * t4;
            *(float2*)&Cfb[(size_t)r0 * L_ + col] =
                make_float2(acc[mi][nj][0], acc[mi][nj][1]);
            *(float2*)&Cfb[(size_t)r1 * L_ + col] =
                make_float2(acc[mi][nj][2], acc[mi][nj][3]);
        }
    }
}

// ---------------------------------------------------------------------------
// nn_out GEMM (fp16 1-term, 4-stage ring): out = inputs + attn @ o_proj
// ---------------------------------------------------------------------------
__global__ __launch_bounds__(NTHREADS, 2) void gemm_nnout(
    const float* __restrict__ inputs_, float* __restrict__ out_)
{
    extern __shared__ char smem[];
    const uint32_t smem_base = smem_u32(smem);

    const int tid  = threadIdx.x;
    const int wid  = tid >> 5;
    const int lane = tid & 31;
    const int g    = lane >> 2;
    const int t4   = lane & 3;
    const int wm   = (wid & 3) * 32;
    const int wn   = (wid >> 2) * 64;

    const int bz = blockIdx.z;
    const int m0 = blockIdx.y * 128;   // l
    const int n0 = blockIdx.x * 128;   // c
    const hf* aH = g_atH + (size_t)bz * L_ * L_;
    const hf* bH = g_otH + (size_t)bz * L_;        // row stride MT_

    float acc[2][8][4] = {};
    gemm_core<2048, 1, 4>(acc, aH, nullptr, L_, m0, bH, nullptr, MT_, n0,
                          smem_base, tid, wm, wn, lane);

    const float* R = inputs_ + (size_t)bz * L_ * C_;
    float* O = out_ + (size_t)bz * L_ * C_;

    #pragma unroll
    for (int mi = 0; mi < 2; ++mi) {
        const int r0 = m0 + wm + mi * 16 + g;
        const int r1 = r0 + 8;
        #pragma unroll
        for (int nj = 0; nj < 8; ++nj) {
            const int col = n0 + wn + nj * 8 + 2 * t4;
            float2 v0 = make_float2(acc[mi][nj][0], acc[mi][nj][1]);
            float2 v1 = make_float2(acc[mi][nj][2], acc[mi][nj][3]);
            const float2 q0 = *(const float2*)&R[(size_t)r0 * C_ + col];
            const float2 q1 = *(const float2*)&R[(size_t)r1 * C_ + col];
            v0.x += q0.x; v0.y += q0.y; v1.x += q1.x; v1.y += q1.y;
            *(float2*)&O[(size_t)r0 * C_ + col] = v0;
            *(float2*)&O[(size_t)r1 * C_ + col] = v1;
        }
    }
}

// ---------------------------------------------------------------------------
// Decompose inputs f32 -> fp16 hi/lo; first blocks also copy biases
// ---------------------------------------------------------------------------
__global__ __launch_bounds__(256) void decomp_inputs(
    const float* __restrict__ src, int n4,
    const float* __restrict__ bx, const float* __restrict__ by,
    const float* __restrict__ bo)
{
    const int i = blockIdx.x * 256 + threadIdx.x;
    if (i < C_) {
        g_bxy[i] = (i < CI_) ? bx[i] : by[i - CI_];
        g_bo[i]  = bo[i];
    }
    if (i >= n4) return;
    const float4 v = ((const float4*)src)[i];
    hf h0, h1, h2, h3, l0, l1, l2, l3;
    splitf(v.x, h0, l0); splitf(v.y, h1, l1);
    splitf(v.z, h2, l2); splitf(v.w, h3, l3);
    ((uint2*)g_inH)[i] = make_uint2(pack2(h0, h1), pack2(h2, h3));
    ((uint2*)g_inL)[i] = make_uint2(pack2(l0, l1), pack2(l2, l3));
}

// ---------------------------------------------------------------------------
// Single prep kernel: z selects Wx / Wy / Wo transpose+decompose (fp16)
// ---------------------------------------------------------------------------
__global__ void prep_weights(const float* __restrict__ Wx,
                             const float* __restrict__ Wy,
                             const float* __restrict__ Wo)
{
    __shared__ float tbuf[32][33];
    const int zz = blockIdx.z;
    const int Cc = (zz == 2) ? C_ : CI_;
    if (blockIdx.x * 32 >= Cc) return;
    const float* src = (zz == 0) ? Wx : (zz == 1) ? Wy : Wo;
    hf* H = (zz == 0) ? g_wxyH : (zz == 1) ? g_wxyH + (size_t)CI_ * C_ : g_wotH;
    hf* L = (zz == 0) ? g_wxyL : (zz == 1) ? g_wxyL + (size_t)CI_ * C_ : g_wotL;

    const int bx = blockIdx.x * 32;
    const int by = blockIdx.y * 32;
    const int x = threadIdx.x, y = threadIdx.y;
    #pragma unroll
    for (int d = 0; d < 32; d += 8)
        tbuf[y + d][x] = src[(size_t)(by + y + d) * Cc + bx + x];
    __syncthreads();
    #pragma unroll
    for (int d = 0; d < 32; d += 8) {
        hf h, l;
        splitf(tbuf[x][y + d], h, l);
        H[(size_t)(bx + y + d) * C_ + by + x] = h;
        L[(size_t)(bx + y + d) * C_ + by + x] = l;
    }
}

// ---------------------------------------------------------------------------
// Softmax over batch axis: f32 logits -> fp16 attn (8 elements per thread)
// ---------------------------------------------------------------------------
__global__ __launch_bounds__(256) void softmax_batch()
{
    const size_t idx = ((size_t)blockIdx.x * 256 + threadIdx.x) * 8;
    const size_t stride = (size_t)L_ * L_;
    float4 v[B_][2];
    float4 mx0 = make_float4(-INFINITY, -INFINITY, -INFINITY, -INFINITY);
    float4 mx1 = mx0;
    #pragma unroll
    for (int b = 0; b < B_; ++b) {
        v[b][0] = *(const float4*)&g_scores[b * stride + idx];
        v[b][1] = *(const float4*)&g_scores[b * stride + idx + 4];
        mx0.x = fmaxf(mx0.x, v[b][0].x); mx0.y = fmaxf(mx0.y, v[b][0].y);
        mx0.z = fmaxf(mx0.z, v[b][0].z); mx0.w = fmaxf(mx0.w, v[b][0].w);
        mx1.x = fmaxf(mx1.x, v[b][1].x); mx1.y = fmaxf(mx1.y, v[b][1].y);
        mx1.z = fmaxf(mx1.z, v[b][1].z); mx1.w = fmaxf(mx1.w, v[b][1].w);
    }
    float4 s0 = make_float4(0.f, 0.f, 0.f, 0.f), s1 = s0;
    #pragma unroll
    for (int b = 0; b < B_; ++b) {
        v[b][0].x = __expf(v[b][0].x - mx0.x); s0.x += v[b][0].x;
        v[b][0].y = __expf(v[b][0].y - mx0.y); s0.y += v[b][0].y;
        v[b][0].z = __expf(v[b][0].z - mx0.z); s0.z += v[b][0].z;
        v[b][0].w = __expf(v[b][0].w - mx0.w); s0.w += v[b][0].w;
        v[b][1].x = __expf(v[b][1].x - mx1.x); s1.x += v[b][1].x;
        v[b][1].y = __expf(v[b][1].y - mx1.y); s1.y += v[b][1].y;
        v[b][1].z = __expf(v[b][1].z - mx1.z); s1.z += v[b][1].z;
        v[b][1].w = __expf(v[b][1].w - mx1.w); s1.w += v[b][1].w;
    }
    const float4 i0 = make_float4(1.f / s0.x, 1.f / s0.y, 1.f / s0.z, 1.f / s0.w);
    const float4 i1 = make_float4(1.f / s1.x, 1.f / s1.y, 1.f / s1.z, 1.f / s1.w);
    #pragma unroll
    for (int b = 0; b < B_; ++b) {
        uint4 o;
        o.x = pack2(__float2half_rn(v[b][0].x * i0.x), __float2half_rn(v[b][0].y * i0.y));
        o.y = pack2(__float2half_rn(v[b][0].z * i0.z), __float2half_rn(v[b][0].w * i0.w));
        o.z = pack2(__float2half_rn(v[b][1].x * i1.x), __float2half_rn(v[b][1].y * i1.y));
        o.w = pack2(__float2half_rn(v[b][1].z * i1.z), __float2half_rn(v[b][1].w * i1.w));
        *(uint4*)&g_atH[b * stride + idx] = o;
    }
}

// ---------------------------------------------------------------------------
// Launch: inputs, Wx, bx, Wy, by, Wo, bo
// ---------------------------------------------------------------------------
extern "C" void kernel_launch(void* const* d_in, const int* in_sizes, int n_in,
                              void* d_out, int out_size)
{
    const float* inputs = (const float*)d_in[0];
    const float* Wx = (const float*)d_in[1];
    const float* bx = (const float*)d_in[2];
    const float* Wy = (const float*)d_in[3];
    const float* by = (const float*)d_in[4];
    const float* Wo = (const float*)d_in[5];
    const float* bo = (const float*)d_in[6];
    float* out = (float*)d_out;

    cudaFuncSetAttribute((const void*)gemm_projot,
                         cudaFuncAttributeMaxDynamicSharedMemorySize, SMEM_TS(3, 3));
    cudaFuncSetAttribute((const void*)gemm_scores,
                         cudaFuncAttributeMaxDynamicSharedMemorySize, SMEM_TS(3, 3));
    cudaFuncSetAttribute((const void*)gemm_nnout,
                         cudaFuncAttributeMaxDynamicSharedMemorySize, SMEM_TS(1, 4));

    // 0) decompose inputs (+bias copies), prep weights
    decomp_inputs<<<(MT_ * C_ / 4 + 255) / 256, 256>>>(inputs, MT_ * C_ / 4, bx, by, bo);
    prep_weights<<<dim3(16, 16, 3), dim3(32, 8)>>>(Wx, Wy, Wo);

    // 1) fused projection (3-term) + o_proj^T (2-term)
    gemm_projot<<<dim3(4, 128, 2), NTHREADS, SMEM_TS(3, 3)>>>();

    // 2) scores[b] = x_proj[b] @ y_proj[b]^T (3-term) -> f32 logits
    gemm_scores<<<dim3(L_ / 128, L_ / 128, B_), NTHREADS, SMEM_TS(3, 3)>>>();

    // 3) softmax over batch -> attn fp16 (single plane)
    softmax_batch<<<(L_ * L_ / 8) / 256, 256>>>();

    // 4) out[b] = inputs[b] + attn[b] @ o_proj[b]  (fp16 1-term, 4-stage)
    gemm_nnout<<<dim3(C_ / 128, L_ / 128, B_), NTHREADS, SMEM_TS(1, 4)>>>(inputs, out);
}

// round 17
// speedup vs baseline: 1.0557x; 1.0279x over previous
#include <cuda_runtime.h>
#include <cuda_fp16.h>
#include <cstdint>
#include <math.h>

// ---------------------------------------------------------------------------
// Problem constants
// ---------------------------------------------------------------------------
#define B_  8
#define L_  2048
#define C_  512
#define CI_ 256
#define MT_ 16384   // B_*L_

typedef __half hf;

// ---------------------------------------------------------------------------
// Scratch (__device__ globals; allocation-free)
// ---------------------------------------------------------------------------
__device__ hf    g_inH [(size_t)MT_ * C_];           // inputs hi  [bl][c]
__device__ hf    g_inL [(size_t)MT_ * C_];           // inputs lo
__device__ hf    g_xyH [(size_t)MT_ * C_];           // [x_proj | y_proj] hi [bl][512]
__device__ hf    g_xyL [(size_t)MT_ * C_];
__device__ hf    g_otH [(size_t)C_ * MT_];           // o_proj^T single plane [c][bl]
__device__ float g_scores[(size_t)B_ * L_ * L_];     // f32 logits
__device__ hf    g_atH [(size_t)B_ * L_ * L_];       // attn single plane [b][l][m]
__device__ hf    g_wxyH[C_ * C_], g_wxyL[C_ * C_];   // [WxT ; WyT], [n][c]
__device__ hf    g_wotH[C_ * C_], g_wotL[C_ * C_];   // WoT [d][c]
__device__ float g_bxy[C_];                          // concat(bx, by)
__device__ float g_bo [C_];                          // bo copy

// ---------------------------------------------------------------------------
// helpers
// ---------------------------------------------------------------------------
__device__ __forceinline__ uint32_t smem_u32(const void* p) {
    uint32_t a;
    asm("{ .reg .u64 t; cvta.to.shared.u64 t, %1; cvt.u32.u64 %0, t; }"
        : "=r"(a) : "l"(p));
    return a;
}
__device__ __forceinline__ void splitf(float v, hf& h, hf& l) {
    h = __float2half_rn(v);
    l = __float2half_rn(v - __half2float(h));
}
__device__ __forceinline__ uint32_t pack2(hf a, hf b) {
    return (uint32_t)__half_as_ushort(a) |
           ((uint32_t)__half_as_ushort(b) << 16);
}
// streaming (evict-first) f32x2 store / f32x4 load for the huge logits tensor
__device__ __forceinline__ void st_cs_f2(float* p, float2 v) {
    asm volatile("st.global.cs.v2.f32 [%0], {%1, %2};" :: "l"(p), "f"(v.x), "f"(v.y)
                 : "memory");
}
__device__ __forceinline__ float4 ld_cs_f4(const float* p) {
    float4 v;
    asm volatile("ld.global.cs.v4.f32 {%0, %1, %2, %3}, [%4];"
                 : "=f"(v.x), "=f"(v.y), "=f"(v.z), "=f"(v.w) : "l"(p));
    return v;
}

#define CP16(dst, src) \
    asm volatile("cp.async.ca.shared.global [%0], [%1], 16;" :: "r"(dst), "l"(src) : "memory")
#define CP_COMMIT() asm volatile("cp.async.commit_group;" ::: "memory")
#define CP_WAIT(n)  asm volatile("cp.async.wait_group %0;" :: "n"(n) : "memory")

#define LDSM_X4(r, a) \
    asm volatile("ldmatrix.sync.aligned.m8n8.x4.shared.b16 {%0,%1,%2,%3}, [%4];" \
        : "=r"((r)[0]), "=r"((r)[1]), "=r"((r)[2]), "=r"((r)[3]) : "r"(a))

__device__ __forceinline__ void mma_f16(float* d, const uint32_t* a, const uint32_t* b) {
    asm("mma.sync.aligned.m16n8k16.row.col.f32.f16.f16.f32 "
        "{%0,%1,%2,%3}, {%4,%5,%6,%7}, {%8,%9}, {%0,%1,%2,%3};"
        : "+f"(d[0]), "+f"(d[1]), "+f"(d[2]), "+f"(d[3])
        : "r"(a[0]), "r"(a[1]), "r"(a[2]), "r"(a[3]), "r"(b[0]), "r"(b[1]));
}

// ---------------------------------------------------------------------------
// GEMM core (R14 shape): 128x128 CTA tile, K-chunk 32, 64B swizzled rows,
// 3-stage ring, single sync/chunk, 8 warps (4M x 2N), warp tile 32x64.
// NTERM=3: A HL, B HL ; NTERM=2: A HL, B H ; NTERM=1: A H, B H
// ---------------------------------------------------------------------------
#define ROWB    64u
#define TILE_B  8192u
#define NSTAGE  3
#define NTHREADS 256
#define SMEM_T(n) (NSTAGE * ((n) + 1) * 8192)

template<int NTERM>
__device__ __forceinline__ void stage_copy(
    uint32_t stage,
    const hf* __restrict__ AH, const hf* __restrict__ AL, int ldA, int m0,
    const hf* __restrict__ BH, const hf* __restrict__ BL, int ldB, int n0,
    int k0, int tid)
{
    constexpr uint32_t B_OFF = (NTERM >= 2 ? 2u : 1u) * TILE_B;
    #pragma unroll
    for (int j = 0; j < 2; ++j) {
        const int seg = tid + NTHREADS * j;
        const int r = seg >> 2, c = seg & 3;
        const int csw = c ^ ((r >> 1) & 3);
        const uint32_t off = (uint32_t)r * ROWB + (uint32_t)csw * 16u;
        const size_t sa = (size_t)(m0 + r) * ldA + k0 + c * 8;
        const size_t sb = (size_t)(n0 + r) * ldB + k0 + c * 8;
        CP16(stage + off, AH + sa);
        if (NTERM >= 2) CP16(stage + TILE_B + off, AL + sa);
        CP16(stage + B_OFF + off, BH + sb);
        if (NTERM == 3) CP16(stage + B_OFF + TILE_B + off, BL + sb);
    }
}

template<int KTOT, int NTERM>
__device__ __forceinline__ void gemm_core(
    float acc[2][8][4],
    const hf* __restrict__ aH, const hf* __restrict__ aL, int ldA, int m0,
    const hf* __restrict__ bH, const hf* __restrict__ bL, int ldB, int n0,
    uint32_t smem_base, int tid, int wm, int wn, int lane)
{
    constexpr int NC = KTOT / 32;
    constexpr uint32_t STG   = (uint32_t)(NTERM + 1) * TILE_B;
    constexpr uint32_t B_OFF = (NTERM >= 2 ? 2u : 1u) * TILE_B;

    const uint32_t key  = (uint32_t)(((lane & 7) >> 1) & 3);
    const uint32_t aRow = (uint32_t)(wm + (lane & 7) + ((lane >> 3) & 1) * 8) * ROWB;
    const uint32_t bRow = (uint32_t)(wn + (lane & 7) + ((lane >> 4) & 1) * 8) * ROWB;
    const uint32_t aCh  = (uint32_t)(lane >> 4);
    const uint32_t bCh  = (uint32_t)((lane >> 3) & 1);

    stage_copy<NTERM>(smem_base, aH, aL, ldA, m0, bH, bL, ldB, n0, 0, tid);
    CP_COMMIT();
    stage_copy<NTERM>(smem_base + STG, aH, aL, ldA, m0, bH, bL, ldB, n0, 32, tid);
    CP_COMMIT();

    uint32_t stage = smem_base;
    for (int kc = 0; kc < NC; ++kc) {
        if (kc + 1 < NC) { CP_WAIT(1); } else { CP_WAIT(0); }
        __syncthreads();

        #pragma unroll
        for (int ks = 0; ks < 2; ++ks) {
            uint32_t ah[2][4], al[2][4];
            const uint32_t aSw = ((uint32_t)(ks * 2) + aCh) ^ key;
            const uint32_t bSw = ((uint32_t)(ks * 2) + bCh) ^ key;
            #pragma unroll
            for (int mi = 0; mi < 2; ++mi) {
                const uint32_t base = stage + aRow + mi * (16u * ROWB) + aSw * 16u;
                LDSM_X4(ah[mi], base);
                if (NTERM >= 2) LDSM_X4(al[mi], base + TILE_B);
            }
            #pragma unroll
            for (int h = 0; h < 2; ++h) {
                uint32_t bh2[8], bl2[8];
                #pragma unroll
                for (int q = 0; q < 2; ++q) {
                    const uint32_t base = stage + B_OFF + bRow
                                        + (uint32_t)(h * 32 + q * 16) * ROWB + bSw * 16u;
                    LDSM_X4(bh2 + q * 4, base);
                    if (NTERM == 3) LDSM_X4(bl2 + q * 4, base + TILE_B);
                }
                #pragma unroll
                for (int njl = 0; njl < 4; ++njl) {
                    const int nj = h * 4 + njl;
                    #pragma unroll
                    for (int mi = 0; mi < 2; ++mi)
                        mma_f16(acc[mi][nj], ah[mi], bh2 + njl * 2);
                }
                if (NTERM == 3) {
                    #pragma unroll
                    for (int njl = 0; njl < 4; ++njl) {
                        const int nj = h * 4 + njl;
                        #pragma unroll
                        for (int mi = 0; mi < 2; ++mi)
                            mma_f16(acc[mi][nj], ah[mi], bl2 + njl * 2);
                    }
                }
                if (NTERM >= 2) {
                    #pragma unroll
                    for (int njl = 0; njl < 4; ++njl) {
                        const int nj = h * 4 + njl;
                        #pragma unroll
                        for (int mi = 0; mi < 2; ++mi)
                            mma_f16(acc[mi][nj], al[mi], bh2 + njl * 2);
                    }
                }
            }
        }

        if (kc + 2 < NC) {
            uint32_t wstage = stage + 2 * STG;
            if (wstage >= smem_base + NSTAGE * STG) wstage -= NSTAGE * STG;
            stage_copy<NTERM>(wstage, aH, aL, ldA, m0, bH, bL, ldB, n0, (kc + 2) * 32, tid);
            CP_COMMIT();
        }
        stage += STG;
        if (stage >= smem_base + NSTAGE * STG) stage = smem_base;
    }
}

// ---------------------------------------------------------------------------
// Fused projection + o_proj^T
// z=0: xy = in @ Wxy^T + bxy[n] -> fp16 HL      (3-term)   grid (4=n, 128=m, .)
// z=1: ot = WoT @ in^T + bo[m]  -> fp16 single  (2-term)   grid (4=m, 128=n, .)
// ---------------------------------------------------------------------------
__global__ __launch_bounds__(NTHREADS, 2) void gemm_projot()
{
    extern __shared__ char smem[];
    const uint32_t smem_base = smem_u32(smem);

    const int tid  = threadIdx.x;
    const int wid  = tid >> 5;
    const int lane = tid & 31;
    const int g    = lane >> 2;
    const int t4   = lane & 3;
    const int wm   = (wid & 3) * 32;
    const int wn   = (wid >> 2) * 64;

    const int zz = blockIdx.z;
    const int m0 = (zz == 0) ? blockIdx.y * 128 : blockIdx.x * 128;
    const int n0 = (zz == 0) ? blockIdx.x * 128 : blockIdx.y * 128;

    float acc[2][8][4] = {};
    if (zz == 0) {
        gemm_core<512, 3>(acc, g_inH, g_inL, C_, m0, g_wxyH, g_wxyL, C_, n0,
                          smem_base, tid, wm, wn, lane);
    } else {
        gemm_core<512, 2>(acc, g_wotH, g_wotL, C_, m0, g_inH, nullptr, C_, n0,
                          smem_base, tid, wm, wn, lane);
    }

    #pragma unroll
    for (int mi = 0; mi < 2; ++mi) {
        const int r0 = m0 + wm + mi * 16 + g;
        const int r1 = r0 + 8;
        const float bm0 = (zz == 1) ? g_bo[r0] : 0.f;
        const float bm1 = (zz == 1) ? g_bo[r1] : 0.f;
        #pragma unroll
        for (int nj = 0; nj < 8; ++nj) {
            const int col = n0 + wn + nj * 8 + 2 * t4;
            float2 v0 = make_float2(acc[mi][nj][0], acc[mi][nj][1]);
            float2 v1 = make_float2(acc[mi][nj][2], acc[mi][nj][3]);
            if (zz == 0) {
                const float2 bb = *(const float2*)&g_bxy[col];
                v0.x += bb.x; v0.y += bb.y; v1.x += bb.x; v1.y += bb.y;
                hf h0, l0, h1, l1;
                splitf(v0.x, h0, l0); splitf(v0.y, h1, l1);
                *(uint32_t*)&g_xyH[(size_t)r0 * C_ + col] = pack2(h0, h1);
                *(uint32_t*)&g_xyL[(size_t)r0 * C_ + col] = pack2(l0, l1);
                splitf(v1.x, h0, l0); splitf(v1.y, h1, l1);
                *(uint32_t*)&g_xyH[(size_t)r1 * C_ + col] = pack2(h0, h1);
                *(uint32_t*)&g_xyL[(size_t)r1 * C_ + col] = pack2(l0, l1);
            } else {
                v0.x += bm0; v0.y += bm0; v1.x += bm1; v1.y += bm1;
                *(uint32_t*)&g_otH[(size_t)r0 * MT_ + col] =
                    pack2(__float2half_rn(v0.x), __float2half_rn(v0.y));
                *(uint32_t*)&g_otH[(size_t)r1 * MT_ + col] =
                    pack2(__float2half_rn(v1.x), __float2half_rn(v1.y));
            }
        }
    }
}

// ---------------------------------------------------------------------------
// scores GEMM (fp16 3-term, f32 out via streaming stores)
// ---------------------------------------------------------------------------
__global__ __launch_bounds__(NTHREADS, 2) void gemm_scores()
{
    extern __shared__ char smem[];
    const uint32_t smem_base = smem_u32(smem);

    const int tid  = threadIdx.x;
    const int wid  = tid >> 5;
    const int lane = tid & 31;
    const int g    = lane >> 2;
    const int t4   = lane & 3;
    const int wm   = (wid & 3) * 32;
    const int wn   = (wid >> 2) * 64;

    const int bz = blockIdx.z;
    const int m0 = blockIdx.y * 128;
    const int n0 = blockIdx.x * 128;
    const hf* aH = g_xyH + (size_t)bz * L_ * C_;
    const hf* aL = g_xyL + (size_t)bz * L_ * C_;
    const hf* bH = aH + CI_;
    const hf* bL = aL + CI_;

    float acc[2][8][4] = {};
    gemm_core<256, 3>(acc, aH, aL, C_, m0, bH, bL, C_, n0, smem_base, tid, wm, wn, lane);

    float* Cfb = g_scores + (size_t)bz * L_ * L_;
    #pragma unroll
    for (int mi = 0; mi < 2; ++mi) {
        const int r0 = m0 + wm + mi * 16 + g;
        const int r1 = r0 + 8;
        #pragma unroll
        for (int nj = 0; nj < 8; ++nj) {
            const int col = n0 + wn + nj * 8 + 2 * t4;
            st_cs_f2(&Cfb[(size_t)r0 * L_ + col],
                     make_float2(acc[mi][nj][0], acc[mi][nj][1]));
            st_cs_f2(&Cfb[(size_t)r1 * L_ + col],
                     make_float2(acc[mi][nj][2], acc[mi][nj][3]));
        }
    }
}

// ---------------------------------------------------------------------------
// nn_out GEMM (fp16 1-term, 3-stage): out = inputs + attn @ o_proj
// ---------------------------------------------------------------------------
__global__ __launch_bounds__(NTHREADS, 2) void gemm_nnout(
    const float* __restrict__ inputs_, float* __restrict__ out_)
{
    extern __shared__ char smem[];
    const uint32_t smem_base = smem_u32(smem);

    const int tid  = threadIdx.x;
    const int wid  = tid >> 5;
    const int lane = tid & 31;
    const int g    = lane >> 2;
    const int t4   = lane & 3;
    const int wm   = (wid & 3) * 32;
    const int wn   = (wid >> 2) * 64;

    const int bz = blockIdx.z;
    const int m0 = blockIdx.y * 128;   // l
    const int n0 = blockIdx.x * 128;   // c
    const hf* aH = g_atH + (size_t)bz * L_ * L_;
    const hf* bH = g_otH + (size_t)bz * L_;        // row stride MT_

    float acc[2][8][4] = {};
    gemm_core<2048, 1>(acc, aH, nullptr, L_, m0, bH, nullptr, MT_, n0,
                       smem_base, tid, wm, wn, lane);

    const float* R = inputs_ + (size_t)bz * L_ * C_;
    float* O = out_ + (size_t)bz * L_ * C_;

    #pragma unroll
    for (int mi = 0; mi < 2; ++mi) {
        const int r0 = m0 + wm + mi * 16 + g;
        const int r1 = r0 + 8;
        #pragma unroll
        for (int nj = 0; nj < 8; ++nj) {
            const int col = n0 + wn + nj * 8 + 2 * t4;
            float2 v0 = make_float2(acc[mi][nj][0], acc[mi][nj][1]);
            float2 v1 = make_float2(acc[mi][nj][2], acc[mi][nj][3]);
            const float2 q0 = *(const float2*)&R[(size_t)r0 * C_ + col];
            const float2 q1 = *(const float2*)&R[(size_t)r1 * C_ + col];
            v0.x += q0.x; v0.y += q0.y; v1.x += q1.x; v1.y += q1.y;
            *(float2*)&O[(size_t)r0 * C_ + col] = v0;
            *(float2*)&O[(size_t)r1 * C_ + col] = v1;
        }
    }
}

// ---------------------------------------------------------------------------
// Fused prep: blocks [0, NDEC) decompose inputs (+bias copies);
// blocks [NDEC, NDEC+768) transpose+decompose Wx/Wy/Wo.
// ---------------------------------------------------------------------------
#define NDEC (MT_ * C_ / 4 / 256)   // 8192 blocks, 4 floats per thread

__global__ __launch_bounds__(256) void prep_all(
    const float* __restrict__ src,
    const float* __restrict__ Wx, const float* __restrict__ Wy,
    const float* __restrict__ Wo,
    const float* __restrict__ bx, const float* __restrict__ by,
    const float* __restrict__ bo)
{
    __shared__ float tbuf[32][33];
    const int tid = threadIdx.x;

    if (blockIdx.x < NDEC) {
        const int i = blockIdx.x * 256 + tid;
        if (i < C_) {
            g_bxy[i] = (i < CI_) ? bx[i] : by[i - CI_];
            g_bo[i]  = bo[i];
        }
        const float4 v = ((const float4*)src)[i];
        hf h0, h1, h2, h3, l0, l1, l2, l3;
        splitf(v.x, h0, l0); splitf(v.y, h1, l1);
        splitf(v.z, h2, l2); splitf(v.w, h3, l3);
        ((uint2*)g_inH)[i] = make_uint2(pack2(h0, h1), pack2(h2, h3));
        ((uint2*)g_inL)[i] = make_uint2(pack2(l0, l1), pack2(l2, l3));
        return;
    }

    // weight prep: 768 blocks = 3 matrices x 16 x 16 tiles
    const int pb = blockIdx.x - NDEC;
    const int zz = pb >> 8;            // 0..2
    const int rem = pb & 255;
    const int bxi = (rem & 15) * 32;   // Cc tile
    const int byi = (rem >> 4) * 32;   // row tile
    const int Cc = (zz == 2) ? C_ : CI_;
    if (bxi >= Cc) return;
    const float* wsrc = (zz == 0) ? Wx : (zz == 1) ? Wy : Wo;
    hf* H = (zz == 0) ? g_wxyH : (zz == 1) ? g_wxyH + (size_t)CI_ * C_ : g_wotH;
    hf* L = (zz == 0) ? g_wxyL : (zz == 1) ? g_wxyL + (size_t)CI_ * C_ : g_wotL;

    const int x = tid & 31, y = tid >> 5;   // 32 x 8
    #pragma unroll
    for (int d = 0; d < 32; d += 8)
        tbuf[y + d][x] = wsrc[(size_t)(byi + y + d) * Cc + bxi + x];
    __syncthreads();
    #pragma unroll
    for (int d = 0; d < 32; d += 8) {
        hf h, l;
        splitf(tbuf[x][y + d], h, l);
        H[(size_t)(bxi + y + d) * C_ + byi + x] = h;
        L[(size_t)(bxi + y + d) * C_ + byi + x] = l;
    }
}

// ---------------------------------------------------------------------------
// Softmax over batch axis: f32 logits (streaming loads) -> fp16 attn
// ---------------------------------------------------------------------------
__global__ __launch_bounds__(256) void softmax_batch()
{
    const size_t idx = ((size_t)blockIdx.x * 256 + threadIdx.x) * 8;
    const size_t stride = (size_t)L_ * L_;
    float4 v[B_][2];
    float4 mx0 = make_float4(-INFINITY, -INFINITY, -INFINITY, -INFINITY);
    float4 mx1 = mx0;
    #pragma unroll
    for (int b = 0; b < B_; ++b) {
        v[b][0] = ld_cs_f4(&g_scores[b * stride + idx]);
        v[b][1] = ld_cs_f4(&g_scores[b * stride + idx + 4]);
        mx0.x = fmaxf(mx0.x, v[b][0].x); mx0.y = fmaxf(mx0.y, v[b][0].y);
        mx0.z = fmaxf(mx0.z, v[b][0].z); mx0.w = fmaxf(mx0.w, v[b][0].w);
        mx1.x = fmaxf(mx1.x, v[b][1].x); mx1.y = fmaxf(mx1.y, v[b][1].y);
        mx1.z = fmaxf(mx1.z, v[b][1].z); mx1.w = fmaxf(mx1.w, v[b][1].w);
    }
    float4 s0 = make_float4(0.f, 0.f, 0.f, 0.f), s1 = s0;
    #pragma unroll
    for (int b = 0; b < B_; ++b) {
        v[b][0].x = __expf(v[b][0].x - mx0.x); s0.x += v[b][0].x;
        v[b][0].y = __expf(v[b][0].y - mx0.y); s0.y += v[b][0].y;
        v[b][0].z = __expf(v[b][0].z - mx0.z); s0.z += v[b][0].z;
        v[b][0].w = __expf(v[b][0].w - mx0.w); s0.w += v[b][0].w;
        v[b][1].x = __expf(v[b][1].x - mx1.x); s1.x += v[b][1].x;
        v[b][1].y = __expf(v[b][1].y - mx1.y); s1.y += v[b][1].y;
        v[b][1].z = __expf(v[b][1].z - mx1.z); s1.z += v[b][1].z;
        v[b][1].w = __expf(v[b][1].w - mx1.w); s1.w += v[b][1].w;
    }
    const float4 i0 = make_float4(1.f / s0.x, 1.f / s0.y, 1.f / s0.z, 1.f / s0.w);
    const float4 i1 = make_float4(1.f / s1.x, 1.f / s1.y, 1.f / s1.z, 1.f / s1.w);
    #pragma unroll
    for (int b = 0; b < B_; ++b) {
        uint4 o;
        o.x = pack2(__float2half_rn(v[b][0].x * i0.x), __float2half_rn(v[b][0].y * i0.y));
        o.y = pack2(__float2half_rn(v[b][0].z * i0.z), __float2half_rn(v[b][0].w * i0.w));
        o.z = pack2(__float2half_rn(v[b][1].x * i1.x), __float2half_rn(v[b][1].y * i1.y));
        o.w = pack2(__float2half_rn(v[b][1].z * i1.z), __float2half_rn(v[b][1].w * i1.w));
        *(uint4*)&g_atH[b * stride + idx] = o;
    }
}

// ---------------------------------------------------------------------------
// Launch: inputs, Wx, bx, Wy, by, Wo, bo
// ---------------------------------------------------------------------------
extern "C" void kernel_launch(void* const* d_in, const int* in_sizes, int n_in,
                              void* d_out, int out_size)
{
    const float* inputs = (const float*)d_in[0];
    const float* Wx = (const float*)d_in[1];
    const float* bx = (const float*)d_in[2];
    const float* Wy = (const float*)d_in[3];
    const float* by = (const float*)d_in[4];
    const float* Wo = (const float*)d_in[5];
    const float* bo = (const float*)d_in[6];
    float* out = (float*)d_out;

    cudaFuncSetAttribute((const void*)gemm_projot,
                         cudaFuncAttributeMaxDynamicSharedMemorySize, SMEM_T(3));
    cudaFuncSetAttribute((const void*)gemm_scores,
                         cudaFuncAttributeMaxDynamicSharedMemorySize, SMEM_T(3));
    cudaFuncSetAttribute((const void*)gemm_nnout,
                         cudaFuncAttributeMaxDynamicSharedMemorySize, SMEM_T(1));

    // 0) fused prep: decompose inputs + biases + weights (one launch)
    prep_all<<<NDEC + 768, 256>>>(inputs, Wx, Wy, Wo, bx, by, bo);

    // 1) fused projection (3-term) + o_proj^T (2-term)
    gemm_projot<<<dim3(4, 128, 2), NTHREADS, SMEM_T(3)>>>();

    // 2) scores[b] = x_proj[b] @ y_proj[b]^T (3-term) -> f32 logits (.cs)
    gemm_scores<<<dim3(L_ / 128, L_ / 128, B_), NTHREADS, SMEM_T(3)>>>();

    // 3) softmax over batch -> attn fp16 (single plane)
    softmax_batch<<<(L_ * L_ / 8) / 256, 256>>>();

    // 4) out[b] = inputs[b] + attn[b] @ o_proj[b]  (fp16 1-term)
    gemm_nnout<<<dim3(C_ / 128, L_ / 128, B_), NTHREADS, SMEM_T(1)>>>(inputs, out);
}